// round 1
// baseline (speedup 1.0000x reference)
#include <cuda_runtime.h>
#include <cuda_bf16.h>
#include <cstdint>

// Problem dims
#define B_  4
#define S_  2048
#define DM_ 2048
#define H_  16
#define HD_ 128
#define SCALE_ 0.08838834764831843f   // 1/sqrt(128)

// Scratch (allocation-free rule: __device__ globals)
__device__ float g_Q[(size_t)B_ * S_ * DM_];      // 64 MB  [B*S, 2048]
__device__ float g_K[(size_t)B_ * S_ * HD_];      // 4 MB   [B*S, 128]
__device__ float g_V[(size_t)B_ * S_ * HD_];      // 4 MB
__device__ float g_attn[(size_t)B_ * S_ * DM_];   // 64 MB  [B*S, H*HD]
__device__ float g_rowsum[(size_t)B_ * H_ * S_];  // 0.5 MB

// ---------------- f32x2 packed-FMA helpers (sm_103a) ----------------
__device__ __forceinline__ void ffma2(unsigned long long& d, unsigned long long a,
                                      unsigned long long b) {
    asm volatile("fma.rn.f32x2 %0, %1, %2, %0;" : "+l"(d) : "l"(a), "l"(b));
}
__device__ __forceinline__ unsigned long long pack2(float x, float y) {
    unsigned long long r;
    asm("mov.b64 %0, {%1, %2};" : "=l"(r) : "f"(x), "f"(y));
    return r;
}
__device__ __forceinline__ float2 unpack2(unsigned long long v) {
    float2 r;
    asm("mov.b64 {%0, %1}, %2;" : "=f"(r.x), "=f"(r.y) : "l"(v));
    return r;
}

// ---------------- zero rowsum ----------------
__global__ void zero_kernel(float* p, int n) {
    int i = blockIdx.x * blockDim.x + threadIdx.x;
    if (i < n) p[i] = 0.0f;
}

// ---------------- generic GEMM: C[M,N] = A[M,K] @ B[K,N] + bias ----------------
// Tiles: BM=BN=128, BK=16, 256 threads, 8x8 per thread, f32x2 accumulators.
__global__ __launch_bounds__(256) void gemm_bias_kernel(
    const float* __restrict__ A, const float* __restrict__ Bm,
    const float* __restrict__ bias, float* __restrict__ C,
    int M, int N, int K)
{
    __shared__ __align__(16) float As[16][128];
    __shared__ __align__(16) float Bs[16][128];

    const int tid = threadIdx.x;
    const int tm = tid >> 4;       // 0..15
    const int tn = tid & 15;       // 0..15
    const int row0 = blockIdx.y * 128;
    const int col0 = blockIdx.x * 128;

    unsigned long long acc[8][4];
#pragma unroll
    for (int i = 0; i < 8; i++)
#pragma unroll
        for (int j = 0; j < 4; j++) acc[i][j] = 0ull;

    for (int k0 = 0; k0 < K; k0 += 16) {
        // A tile 128x16 -> As[k][m] (transposed)
#pragma unroll
        for (int i = 0; i < 2; i++) {
            int idx = tid * 2 + i;          // 0..511
            int r = idx >> 2;               // 0..127
            int kq = (idx & 3) << 2;        // 0,4,8,12
            float4 v = *(const float4*)&A[(size_t)(row0 + r) * K + k0 + kq];
            As[kq + 0][r] = v.x; As[kq + 1][r] = v.y;
            As[kq + 2][r] = v.z; As[kq + 3][r] = v.w;
        }
        // B tile 16x128 -> Bs[k][n]
#pragma unroll
        for (int i = 0; i < 2; i++) {
            int idx = tid * 2 + i;
            int r = idx >> 5;               // 0..15
            int cq = (idx & 31) << 2;       // 0..124
            *(float4*)&Bs[r][cq] = *(const float4*)&Bm[(size_t)(k0 + r) * N + col0 + cq];
        }
        __syncthreads();

#pragma unroll
        for (int kk = 0; kk < 16; kk++) {
            float4 a0 = *(const float4*)&As[kk][tm * 8];
            float4 a1 = *(const float4*)&As[kk][tm * 8 + 4];
            ulonglong2 bb0 = *(const ulonglong2*)&Bs[kk][tn * 8];
            ulonglong2 bb1 = *(const ulonglong2*)&Bs[kk][tn * 8 + 4];
            unsigned long long bv[4] = {bb0.x, bb0.y, bb1.x, bb1.y};
            float av[8] = {a0.x, a0.y, a0.z, a0.w, a1.x, a1.y, a1.z, a1.w};
#pragma unroll
            for (int i = 0; i < 8; i++) {
                unsigned long long ad = pack2(av[i], av[i]);
#pragma unroll
                for (int j = 0; j < 4; j++) ffma2(acc[i][j], ad, bv[j]);
            }
        }
        __syncthreads();
    }

    float bz[8];
#pragma unroll
    for (int j = 0; j < 8; j++) bz[j] = bias[col0 + tn * 8 + j];
#pragma unroll
    for (int i = 0; i < 8; i++) {
        int r = row0 + tm * 8 + i;
        float o[8];
#pragma unroll
        for (int j = 0; j < 4; j++) {
            float2 p = unpack2(acc[i][j]);
            o[2 * j] = p.x + bz[2 * j];
            o[2 * j + 1] = p.y + bz[2 * j + 1];
        }
        float* cp = &C[(size_t)r * N + col0 + tn * 8];
        *(float4*)cp = make_float4(o[0], o[1], o[2], o[3]);
        *(float4*)(cp + 4) = make_float4(o[4], o[5], o[6], o[7]);
    }
}

// ---------------- scores: E = exp(scale * Q Kt), unnormalized, + rowsums ----------------
// grid (S/128, S/128, B*H). A[m][k]=Q[b,m,h,:], B[n][k]=K[b,n,:]  (NT GEMM, K=128)
__global__ __launch_bounds__(256) void scores_kernel(
    const float* __restrict__ Q, const float* __restrict__ Kb,
    float* __restrict__ scores, float* __restrict__ rowsum)
{
    __shared__ __align__(16) float As[16][128];
    __shared__ __align__(16) float Bs[16][128];
    __shared__ float red[16][128];

    const int tid = threadIdx.x;
    const int tm = tid >> 4, tn = tid & 15;
    const int bh = blockIdx.z;
    const int b = bh >> 4;
    const int h = bh & 15;
    const int row0 = blockIdx.y * 128;
    const int col0 = blockIdx.x * 128;

    const float* Abase = Q + (size_t)b * S_ * DM_ + h * HD_;   // [m*DM_ + k]
    const float* Bbase = Kb + (size_t)b * S_ * HD_;            // [n*HD_ + k]

    unsigned long long acc[8][4];
#pragma unroll
    for (int i = 0; i < 8; i++)
#pragma unroll
        for (int j = 0; j < 4; j++) acc[i][j] = 0ull;

    for (int k0 = 0; k0 < HD_; k0 += 16) {
#pragma unroll
        for (int i = 0; i < 2; i++) {
            int idx = tid * 2 + i;
            int r = idx >> 2;
            int kq = (idx & 3) << 2;
            float4 v = *(const float4*)&Abase[(size_t)(row0 + r) * DM_ + k0 + kq];
            As[kq + 0][r] = v.x; As[kq + 1][r] = v.y;
            As[kq + 2][r] = v.z; As[kq + 3][r] = v.w;
            float4 w = *(const float4*)&Bbase[(size_t)(col0 + r) * HD_ + k0 + kq];
            Bs[kq + 0][r] = w.x; Bs[kq + 1][r] = w.y;
            Bs[kq + 2][r] = w.z; Bs[kq + 3][r] = w.w;
        }
        __syncthreads();
#pragma unroll
        for (int kk = 0; kk < 16; kk++) {
            float4 a0 = *(const float4*)&As[kk][tm * 8];
            float4 a1 = *(const float4*)&As[kk][tm * 8 + 4];
            ulonglong2 bb0 = *(const ulonglong2*)&Bs[kk][tn * 8];
            ulonglong2 bb1 = *(const ulonglong2*)&Bs[kk][tn * 8 + 4];
            unsigned long long bv[4] = {bb0.x, bb0.y, bb1.x, bb1.y};
            float av[8] = {a0.x, a0.y, a0.z, a0.w, a1.x, a1.y, a1.z, a1.w};
#pragma unroll
            for (int i = 0; i < 8; i++) {
                unsigned long long ad = pack2(av[i], av[i]);
#pragma unroll
                for (int j = 0; j < 4; j++) ffma2(acc[i][j], ad, bv[j]);
            }
        }
        __syncthreads();
    }

    // epilogue: e = exp(scale*l); write; partial row sums
    float sums[8];
#pragma unroll
    for (int i = 0; i < 8; i++) {
        float o[8];
#pragma unroll
        for (int j = 0; j < 4; j++) {
            float2 p = unpack2(acc[i][j]);
            o[2 * j] = __expf(p.x * SCALE_);
            o[2 * j + 1] = __expf(p.y * SCALE_);
        }
        float s = 0.0f;
#pragma unroll
        for (int j = 0; j < 8; j++) s += o[j];
        sums[i] = s;
        size_t off = ((size_t)(bh * S_ + row0 + tm * 8 + i)) * S_ + col0 + tn * 8;
        *(float4*)&scores[off] = make_float4(o[0], o[1], o[2], o[3]);
        *(float4*)&scores[off + 4] = make_float4(o[4], o[5], o[6], o[7]);
    }
#pragma unroll
    for (int i = 0; i < 8; i++) red[tn][tm * 8 + i] = sums[i];
    __syncthreads();
    if (tid < 128) {
        float s = 0.0f;
#pragma unroll
        for (int t = 0; t < 16; t++) s += red[t][tid];
        atomicAdd(&rowsum[(size_t)bh * S_ + row0 + tid], s);
    }
}

// ---------------- normalize scores in place + PV GEMM ----------------
// grid (S/128, B*H). Per block: 128 q-rows, full HD=128 output, loop keys in 16s.
__global__ __launch_bounds__(256) void softmax_pv_kernel(
    float* __restrict__ scores, const float* __restrict__ rowsum,
    const float* __restrict__ Vb, float* __restrict__ attn)
{
    __shared__ __align__(16) float Ps[16][128];
    __shared__ __align__(16) float Vs[16][128];
    __shared__ float rinv[128];

    const int tid = threadIdx.x;
    const int tm = tid >> 4, tn = tid & 15;
    const int bh = blockIdx.y;
    const int b = bh >> 4;
    const int h = bh & 15;
    const int row0 = blockIdx.x * 128;

    if (tid < 128) rinv[tid] = 1.0f / rowsum[(size_t)bh * S_ + row0 + tid];
    __syncthreads();

    unsigned long long acc[8][4];
#pragma unroll
    for (int i = 0; i < 8; i++)
#pragma unroll
        for (int j = 0; j < 4; j++) acc[i][j] = 0ull;

    float* srow = scores + ((size_t)bh * S_ + row0) * S_;
    const float* vbase = Vb + (size_t)b * S_ * HD_;

    for (int k0 = 0; k0 < S_; k0 += 16) {
#pragma unroll
        for (int i = 0; i < 2; i++) {
            int idx = tid * 2 + i;
            int r = idx >> 2;                 // q row 0..127
            int kq = (idx & 3) << 2;
            float4 e = *(const float4*)&srow[(size_t)r * S_ + k0 + kq];
            float ri = rinv[r];
            e.x *= ri; e.y *= ri; e.z *= ri; e.w *= ri;
            *(float4*)&srow[(size_t)r * S_ + k0 + kq] = e;   // normalized scores out
            Ps[kq + 0][r] = e.x; Ps[kq + 1][r] = e.y;
            Ps[kq + 2][r] = e.z; Ps[kq + 3][r] = e.w;
        }
#pragma unroll
        for (int i = 0; i < 2; i++) {
            int idx = tid * 2 + i;
            int r = idx >> 5;                 // 0..15
            int cq = (idx & 31) << 2;
            *(float4*)&Vs[r][cq] = *(const float4*)&vbase[(size_t)(k0 + r) * HD_ + cq];
        }
        __syncthreads();
#pragma unroll
        for (int kk = 0; kk < 16; kk++) {
            float4 a0 = *(const float4*)&Ps[kk][tm * 8];
            float4 a1 = *(const float4*)&Ps[kk][tm * 8 + 4];
            ulonglong2 bb0 = *(const ulonglong2*)&Vs[kk][tn * 8];
            ulonglong2 bb1 = *(const ulonglong2*)&Vs[kk][tn * 8 + 4];
            unsigned long long bv[4] = {bb0.x, bb0.y, bb1.x, bb1.y};
            float av[8] = {a0.x, a0.y, a0.z, a0.w, a1.x, a1.y, a1.z, a1.w};
#pragma unroll
            for (int i = 0; i < 8; i++) {
                unsigned long long ad = pack2(av[i], av[i]);
#pragma unroll
                for (int j = 0; j < 4; j++) ffma2(acc[i][j], ad, bv[j]);
            }
        }
        __syncthreads();
    }

    // attn [B,S,H,HD]
#pragma unroll
    for (int i = 0; i < 8; i++) {
        int m = row0 + tm * 8 + i;
        size_t off = ((size_t)(b * S_ + m)) * DM_ + h * HD_ + tn * 8;
        float o[8];
#pragma unroll
        for (int j = 0; j < 4; j++) {
            float2 p = unpack2(acc[i][j]);
            o[2 * j] = p.x; o[2 * j + 1] = p.y;
        }
        *(float4*)&attn[off] = make_float4(o[0], o[1], o[2], o[3]);
        *(float4*)&attn[off + 4] = make_float4(o[4], o[5], o[6], o[7]);
    }
}

// ---------------- launch ----------------
extern "C" void kernel_launch(void* const* d_in, const int* in_sizes, int n_in,
                              void* d_out, int out_size)
{
    const float* x  = (const float*)d_in[0];
    const float* Wq = (const float*)d_in[1];
    const float* bq = (const float*)d_in[2];
    const float* Wk = (const float*)d_in[3];
    const float* bk = (const float*)d_in[4];
    const float* Wv = (const float*)d_in[5];
    const float* bv = (const float*)d_in[6];
    const float* Wo = (const float*)d_in[7];
    const float* bo = (const float*)d_in[8];

    float* out = (float*)d_out;                                  // [B,S,D]
    float* scores = out + (size_t)B_ * S_ * DM_;                 // [B,H,S,S]

    float *pQ, *pK, *pV, *pAttn, *pRS;
    cudaGetSymbolAddress((void**)&pQ, g_Q);
    cudaGetSymbolAddress((void**)&pK, g_K);
    cudaGetSymbolAddress((void**)&pV, g_V);
    cudaGetSymbolAddress((void**)&pAttn, g_attn);
    cudaGetSymbolAddress((void**)&pRS, g_rowsum);

    const int M = B_ * S_;                         // 8192
    zero_kernel<<<(B_ * H_ * S_ + 255) / 256, 256>>>(pRS, B_ * H_ * S_);

    gemm_bias_kernel<<<dim3(DM_ / 128, M / 128), 256>>>(x, Wq, bq, pQ, M, DM_, DM_);
    gemm_bias_kernel<<<dim3(HD_ / 128, M / 128), 256>>>(x, Wk, bk, pK, M, HD_, DM_);
    gemm_bias_kernel<<<dim3(HD_ / 128, M / 128), 256>>>(x, Wv, bv, pV, M, HD_, DM_);

    scores_kernel<<<dim3(S_ / 128, S_ / 128, B_ * H_), 256>>>(pQ, pK, scores, pRS);
    softmax_pv_kernel<<<dim3(S_ / 128, B_ * H_), 256>>>(scores, pRS, pV, pAttn);

    gemm_bias_kernel<<<dim3(DM_ / 128, M / 128), 256>>>(pAttn, Wo, bo, out, M, DM_, DM_);
}

// round 3
// speedup vs baseline: 1.7919x; 1.7919x over previous
#include <cuda_runtime.h>
#include <cuda_bf16.h>
#include <cstdint>

// Problem dims
#define B_  4
#define S_  2048
#define DM_ 2048
#define H_  16
#define HD_ 128
#define SCALE_ 0.08838834764831843f   // 1/sqrt(128)

// ---------------- scratch (__device__ globals: allocation-free rule) ----------------
__device__ float g_Q[(size_t)B_ * S_ * DM_];        // 64 MB
__device__ float g_K[(size_t)B_ * S_ * HD_];        // 4 MB  [B*S,128] K-major
__device__ float g_Vt[(size_t)B_ * HD_ * S_];       // 4 MB  [B][128][2048]
__device__ float g_attn[(size_t)B_ * S_ * DM_];     // 64 MB
__device__ float g_rowsum[(size_t)B_ * H_ * S_];    // 0.5 MB
__device__ float g_WqT[(size_t)DM_ * DM_];
__device__ float g_WkT[(size_t)HD_ * DM_];
__device__ float g_WvT[(size_t)HD_ * DM_];
__device__ float g_WoT[(size_t)DM_ * DM_];

// ---------------- smem layout ----------------
// operands (union'd with staging):
//   Ah @0 (128x40 bf16 = 10240B), Al @10240, Bh @20480, Bl @30720  (total 40960)
// staging fp32 128x132 @0 (67584 B)  -- used after compute loop
// AUX (bias/rinv) @67584 (512B), RED @68096 (1KB)
#define A_HI_OFF 0
#define A_LO_OFF 10240
#define B_HI_OFF 20480
#define B_LO_OFF 30720
#define AUX_OFF  67584
#define RED_OFF  68096
#define SMEM_BYTES 69632
#define LDT 40            // padded smem row length (bf16 elems) for 32-wide K tile

// ---------------- helpers ----------------
__device__ __forceinline__ uint32_t smem_u32(const void* p) {
    uint32_t a;
    asm("{ .reg .u64 t; cvta.to.shared.u64 t, %1; cvt.u32.u64 %0, t; }" : "=r"(a) : "l"(p));
    return a;
}
__device__ __forceinline__ void ldsm4(uint32_t* r, uint32_t a) {
    asm volatile("ldmatrix.sync.aligned.m8n8.x4.shared.b16 {%0,%1,%2,%3}, [%4];"
        : "=r"(r[0]), "=r"(r[1]), "=r"(r[2]), "=r"(r[3]) : "r"(a));
}
__device__ __forceinline__ void mma_bf16(float* d, const uint32_t* a, uint32_t b0, uint32_t b1) {
    asm volatile("mma.sync.aligned.m16n8k16.row.col.f32.bf16.bf16.f32 "
        "{%0,%1,%2,%3}, {%4,%5,%6,%7}, {%8,%9}, {%0,%1,%2,%3};"
        : "+f"(d[0]), "+f"(d[1]), "+f"(d[2]), "+f"(d[3])
        : "r"(a[0]), "r"(a[1]), "r"(a[2]), "r"(a[3]), "r"(b0), "r"(b1));
}
__device__ __forceinline__ uint32_t bits2(__nv_bfloat162 h) {
    return *reinterpret_cast<uint32_t*>(&h);
}
__device__ __forceinline__ void split4(float4 v, uint32_t& h0, uint32_t& h1,
                                       uint32_t& l0, uint32_t& l1) {
    __nv_bfloat162 a = __floats2bfloat162_rn(v.x, v.y);
    __nv_bfloat162 b = __floats2bfloat162_rn(v.z, v.w);
    float2 fa = __bfloat1622float2(a);
    float2 fb = __bfloat1622float2(b);
    __nv_bfloat162 c = __floats2bfloat162_rn(v.x - fa.x, v.y - fa.y);
    __nv_bfloat162 d = __floats2bfloat162_rn(v.z - fb.x, v.w - fb.y);
    h0 = bits2(a); h1 = bits2(b); l0 = bits2(c); l1 = bits2(d);
}

// one bf16 term: acc += A_term @ B_term^T for this warp's 32x64 patch, k16 slice
__device__ __forceinline__ void term_mma(float (*acc)[8][4],
    const __nv_bfloat16* As, const __nv_bfloat16* Bs,
    int wm, int wn, int lane, int kk)
{
    uint32_t a[2][4], b[4][4];
    const int ar = lane & 15;
    const int ac = kk + ((lane >> 4) << 3);
#pragma unroll
    for (int mt = 0; mt < 2; mt++)
        ldsm4(a[mt], smem_u32(As + (wm * 32 + mt * 16 + ar) * LDT + ac));
#pragma unroll
    for (int p = 0; p < 4; p++)
        ldsm4(b[p], smem_u32(Bs + (wn * 64 + p * 16 + ar) * LDT + ac));
#pragma unroll
    for (int mt = 0; mt < 2; mt++)
#pragma unroll
        for (int p = 0; p < 4; p++) {
            mma_bf16(acc[mt][2 * p],     a[mt], b[p][0], b[p][2]);
            mma_bf16(acc[mt][2 * p + 1], a[mt], b[p][1], b[p][3]);
        }
}

// core: acc = A[128,K] @ Bt[128,K]^T  (3-term bf16 split). PV: normalize A rows by
// rinv and write normalized values back to gmem while loading.
template<bool PV>
__device__ __forceinline__ void gemm_core(
    float (*acc)[8][4], float* __restrict__ A, size_t lda,
    const float* __restrict__ Bt, size_t ldb, int Kdim,
    char* smem, const float* __restrict__ rinv)
{
    const int tid = threadIdx.x;
    const int wid = tid >> 5, lane = tid & 31;
    const int wm = wid & 3, wn = wid >> 2;
    __nv_bfloat16* Ah = (__nv_bfloat16*)(smem + A_HI_OFF);
    __nv_bfloat16* Al = (__nv_bfloat16*)(smem + A_LO_OFF);
    __nv_bfloat16* Bh = (__nv_bfloat16*)(smem + B_HI_OFF);
    __nv_bfloat16* Bl = (__nv_bfloat16*)(smem + B_LO_OFF);

#pragma unroll 1
    for (int k0 = 0; k0 < Kdim; k0 += 32) {
        __syncthreads();
#pragma unroll
        for (int i = 0; i < 4; i++) {
            int idx = i * 256 + tid;
            int r = idx >> 3, c = (idx & 7) << 2;
            float4 v = *(const float4*)(A + (size_t)r * lda + k0 + c);
            if (PV) {
                float ri = rinv[r];
                v.x *= ri; v.y *= ri; v.z *= ri; v.w *= ri;
                *(float4*)(A + (size_t)r * lda + k0 + c) = v;
            }
            uint32_t h0, h1, l0, l1; split4(v, h0, h1, l0, l1);
            int o = r * LDT + c;
            *(uint2*)(Ah + o) = make_uint2(h0, h1);
            *(uint2*)(Al + o) = make_uint2(l0, l1);
        }
#pragma unroll
        for (int i = 0; i < 4; i++) {
            int idx = i * 256 + tid;
            int r = idx >> 3, c = (idx & 7) << 2;
            float4 v = *(const float4*)(Bt + (size_t)r * ldb + k0 + c);
            uint32_t h0, h1, l0, l1; split4(v, h0, h1, l0, l1);
            int o = r * LDT + c;
            *(uint2*)(Bh + o) = make_uint2(h0, h1);
            *(uint2*)(Bl + o) = make_uint2(l0, l1);
        }
        __syncthreads();
#pragma unroll
        for (int kk = 0; kk < 32; kk += 16) {
            term_mma(acc, Ah, Bh, wm, wn, lane, kk);
            term_mma(acc, Ah, Bl, wm, wn, lane, kk);
            term_mma(acc, Al, Bh, wm, wn, lane, kk);
        }
    }
    __syncthreads();   // before staging reuses operand smem
}

// stage acc (fp32) into smem [128][132]
__device__ __forceinline__ void stage_acc(float (*acc)[8][4], float* stg, int wid, int lane) {
    int wm = wid & 3, wn = wid >> 2;
    int r0 = wm * 32 + (lane >> 2), c0 = wn * 64 + (lane & 3) * 2;
#pragma unroll
    for (int mt = 0; mt < 2; mt++)
#pragma unroll
        for (int nt = 0; nt < 8; nt++) {
            int r = r0 + mt * 16, c = c0 + nt * 8;
            *(float2*)&stg[r * 132 + c] = make_float2(acc[mt][nt][0], acc[mt][nt][1]);
            *(float2*)&stg[(r + 8) * 132 + c] = make_float2(acc[mt][nt][2], acc[mt][nt][3]);
        }
}

// ---------------- misc kernels ----------------
__global__ void transpose_kernel(const float* __restrict__ src, float* __restrict__ dst,
                                 int M, int N) {
    __shared__ float t[32][33];
    int bx = blockIdx.x * 32, by = blockIdx.y * 32;
    int x = threadIdx.x, y0 = threadIdx.y;
#pragma unroll
    for (int j = 0; j < 32; j += 8)
        t[y0 + j][x] = src[(size_t)(by + y0 + j) * N + bx + x];
    __syncthreads();
#pragma unroll
    for (int j = 0; j < 32; j += 8)
        dst[(size_t)(bx + y0 + j) * M + by + x] = t[x][y0 + j];
}
__global__ void zero_kernel(float* p, int n) {
    int i = blockIdx.x * blockDim.x + threadIdx.x;
    if (i < n) p[i] = 0.0f;
}

// ---------------- NT GEMM + bias: C[M,N] = A @ Bt^T + bias ----------------
__global__ __launch_bounds__(256) void mma_gemm_bias(
    const float* __restrict__ A, size_t lda,
    const float* __restrict__ Bt, size_t ldb,
    const float* __restrict__ bias,
    float* __restrict__ C, size_t ldc, int Kdim)
{
    extern __shared__ __align__(16) char smem[];
    const int tid = threadIdx.x, wid = tid >> 5, lane = tid & 31;
    const int row0 = blockIdx.y * 128, col0 = blockIdx.x * 128;

    float* bs = (float*)(smem + AUX_OFF);
    if (tid < 128) bs[tid] = bias[col0 + tid];

    float acc[2][8][4];
#pragma unroll
    for (int i = 0; i < 2; i++)
#pragma unroll
        for (int j = 0; j < 8; j++)
#pragma unroll
            for (int q = 0; q < 4; q++) acc[i][j][q] = 0.0f;

    gemm_core<false>(acc, (float*)(A + (size_t)row0 * lda), lda,
                     Bt + (size_t)col0 * ldb, ldb, Kdim, smem, nullptr);

    float* stg = (float*)smem;
    stage_acc(acc, stg, wid, lane);
    __syncthreads();
#pragma unroll 1
    for (int i = 0; i < 16; i++) {
        int idx = i * 256 + tid;
        int rr = idx >> 5, c4 = (idx & 31) << 2;
        float4 v = *(float4*)&stg[rr * 132 + c4];
        v.x += bs[c4]; v.y += bs[c4 + 1]; v.z += bs[c4 + 2]; v.w += bs[c4 + 3];
        *(float4*)&C[(size_t)(row0 + rr) * ldc + col0 + c4] = v;
    }
}

// ---------------- V projection with transposed epilogue ----------------
__global__ __launch_bounds__(256) void mma_vproj(
    const float* __restrict__ A, const float* __restrict__ Bt,
    const float* __restrict__ bias, float* __restrict__ Vt)
{
    extern __shared__ __align__(16) char smem[];
    const int tid = threadIdx.x, wid = tid >> 5, lane = tid & 31;
    const int row0 = blockIdx.y * 128;

    float* bs = (float*)(smem + AUX_OFF);
    if (tid < 128) bs[tid] = bias[tid];

    float acc[2][8][4];
#pragma unroll
    for (int i = 0; i < 2; i++)
#pragma unroll
        for (int j = 0; j < 8; j++)
#pragma unroll
            for (int q = 0; q < 4; q++) acc[i][j][q] = 0.0f;

    gemm_core<false>(acc, (float*)(A + (size_t)row0 * DM_), DM_, Bt, DM_, DM_, smem, nullptr);

    float* stg = (float*)smem;
    stage_acc(acc, stg, wid, lane);
    __syncthreads();
    int b = row0 >> 11;            // row0 / S_
    int s0 = row0 & (S_ - 1);
    float* Vb = Vt + (size_t)b * HD_ * S_;
#pragma unroll 1
    for (int i = 0; i < 64; i++) {
        int idx = i * 256 + tid;
        int m = idx & 127, n = idx >> 7;
        Vb[(size_t)n * S_ + s0 + m] = stg[m * 132 + n] + bs[n];
    }
}

// ---------------- scores: E = exp(scale * Q Kt) + rowsums ----------------
__global__ __launch_bounds__(256) void mma_scores(
    const float* __restrict__ Q, const float* __restrict__ Kb,
    float* __restrict__ scores, float* __restrict__ rowsum)
{
    extern __shared__ __align__(16) char smem[];
    const int tid = threadIdx.x, wid = tid >> 5, lane = tid & 31;
    const int bh = blockIdx.z;
    const int b = bh >> 4, h = bh & 15;
    const int row0 = blockIdx.y * 128, col0 = blockIdx.x * 128;

    float acc[2][8][4];
#pragma unroll
    for (int i = 0; i < 2; i++)
#pragma unroll
        for (int j = 0; j < 8; j++)
#pragma unroll
            for (int q = 0; q < 4; q++) acc[i][j][q] = 0.0f;

    gemm_core<false>(acc,
        (float*)(Q + ((size_t)b * S_ + row0) * DM_ + h * HD_), DM_,
        Kb + ((size_t)b * S_ + col0) * HD_, HD_, HD_, smem, nullptr);

    // exp transform + staging + register row-sums
    float* stg = (float*)smem;
    float* red = (float*)(smem + RED_OFF);
    const int wm = wid & 3, wn = wid >> 2;
    const int r0 = wm * 32 + (lane >> 2), c0 = wn * 64 + (lane & 3) * 2;
    float sums[2][2] = {{0.f, 0.f}, {0.f, 0.f}};
#pragma unroll
    for (int mt = 0; mt < 2; mt++)
#pragma unroll
        for (int nt = 0; nt < 8; nt++) {
            float e0 = __expf(acc[mt][nt][0] * SCALE_);
            float e1 = __expf(acc[mt][nt][1] * SCALE_);
            float e2 = __expf(acc[mt][nt][2] * SCALE_);
            float e3 = __expf(acc[mt][nt][3] * SCALE_);
            int r = r0 + mt * 16, c = c0 + nt * 8;
            *(float2*)&stg[r * 132 + c] = make_float2(e0, e1);
            *(float2*)&stg[(r + 8) * 132 + c] = make_float2(e2, e3);
            sums[mt][0] += e0 + e1;
            sums[mt][1] += e2 + e3;
        }
#pragma unroll
    for (int mt = 0; mt < 2; mt++)
#pragma unroll
        for (int hh = 0; hh < 2; hh++) {
            float v = sums[mt][hh];
            v += __shfl_xor_sync(0xFFFFFFFFu, v, 1);
            v += __shfl_xor_sync(0xFFFFFFFFu, v, 2);
            sums[mt][hh] = v;
        }
    if ((lane & 3) == 0) {
#pragma unroll
        for (int mt = 0; mt < 2; mt++)
#pragma unroll
            for (int hh = 0; hh < 2; hh++)
                red[(wm * 32 + mt * 16 + hh * 8 + (lane >> 2)) * 2 + wn] = sums[mt][hh];
    }
    __syncthreads();
    if (tid < 128)
        atomicAdd(&rowsum[(size_t)bh * S_ + row0 + tid], red[tid * 2] + red[tid * 2 + 1]);

    float* Crow = scores + ((size_t)bh * S_ + row0) * S_ + col0;
#pragma unroll 1
    for (int i = 0; i < 16; i++) {
        int idx = i * 256 + tid;
        int rr = idx >> 5, c4 = (idx & 31) << 2;
        *(float4*)&Crow[(size_t)rr * S_ + c4] = *(float4*)&stg[rr * 132 + c4];
    }
}

// ---------------- normalize scores in place + PV ----------------
__global__ __launch_bounds__(256) void mma_softmax_pv(
    float* __restrict__ scores, const float* __restrict__ rowsum,
    const float* __restrict__ Vt, float* __restrict__ attn)
{
    extern __shared__ __align__(16) char smem[];
    const int tid = threadIdx.x, wid = tid >> 5, lane = tid & 31;
    const int bh = blockIdx.y;
    const int b = bh >> 4, h = bh & 15;
    const int row0 = blockIdx.x * 128;

    float* rinv = (float*)(smem + AUX_OFF);
    if (tid < 128) rinv[tid] = 1.0f / rowsum[(size_t)bh * S_ + row0 + tid];
    __syncthreads();

    float acc[2][8][4];
#pragma unroll
    for (int i = 0; i < 2; i++)
#pragma unroll
        for (int j = 0; j < 8; j++)
#pragma unroll
            for (int q = 0; q < 4; q++) acc[i][j][q] = 0.0f;

    gemm_core<true>(acc,
        scores + ((size_t)bh * S_ + row0) * S_, S_,
        Vt + (size_t)b * HD_ * S_, S_, S_, smem, rinv);

    float* stg = (float*)smem;
    stage_acc(acc, stg, wid, lane);
    __syncthreads();
    float* Cb = attn + ((size_t)b * S_ + row0) * DM_ + h * HD_;
#pragma unroll 1
    for (int i = 0; i < 16; i++) {
        int idx = i * 256 + tid;
        int rr = idx >> 5, c4 = (idx & 31) << 2;
        *(float4*)&Cb[(size_t)rr * DM_ + c4] = *(float4*)&stg[rr * 132 + c4];
    }
}

// ---------------- launch ----------------
extern "C" void kernel_launch(void* const* d_in, const int* in_sizes, int n_in,
                              void* d_out, int out_size)
{
    const float* x  = (const float*)d_in[0];
    const float* Wq = (const float*)d_in[1];
    const float* bq = (const float*)d_in[2];
    const float* Wk = (const float*)d_in[3];
    const float* bk = (const float*)d_in[4];
    const float* Wv = (const float*)d_in[5];
    const float* bv = (const float*)d_in[6];
    const float* Wo = (const float*)d_in[7];
    const float* bo = (const float*)d_in[8];

    float* out = (float*)d_out;
    float* scores = out + (size_t)B_ * S_ * DM_;

    float *pQ, *pK, *pVt, *pAttn, *pRS, *pWqT, *pWkT, *pWvT, *pWoT;
    cudaGetSymbolAddress((void**)&pQ, g_Q);
    cudaGetSymbolAddress((void**)&pK, g_K);
    cudaGetSymbolAddress((void**)&pVt, g_Vt);
    cudaGetSymbolAddress((void**)&pAttn, g_attn);
    cudaGetSymbolAddress((void**)&pRS, g_rowsum);
    cudaGetSymbolAddress((void**)&pWqT, g_WqT);
    cudaGetSymbolAddress((void**)&pWkT, g_WkT);
    cudaGetSymbolAddress((void**)&pWvT, g_WvT);
    cudaGetSymbolAddress((void**)&pWoT, g_WoT);

    static int smem_set = 0;
    if (!smem_set) {
        cudaFuncSetAttribute(mma_gemm_bias, cudaFuncAttributeMaxDynamicSharedMemorySize, SMEM_BYTES);
        cudaFuncSetAttribute(mma_vproj, cudaFuncAttributeMaxDynamicSharedMemorySize, SMEM_BYTES);
        cudaFuncSetAttribute(mma_scores, cudaFuncAttributeMaxDynamicSharedMemorySize, SMEM_BYTES);
        cudaFuncSetAttribute(mma_softmax_pv, cudaFuncAttributeMaxDynamicSharedMemorySize, SMEM_BYTES);
        smem_set = 1;
    }

    transpose_kernel<<<dim3(DM_ / 32, DM_ / 32), dim3(32, 8)>>>(Wq, pWqT, DM_, DM_);
    transpose_kernel<<<dim3(HD_ / 32, DM_ / 32), dim3(32, 8)>>>(Wk, pWkT, DM_, HD_);
    transpose_kernel<<<dim3(HD_ / 32, DM_ / 32), dim3(32, 8)>>>(Wv, pWvT, DM_, HD_);
    transpose_kernel<<<dim3(DM_ / 32, DM_ / 32), dim3(32, 8)>>>(Wo, pWoT, DM_, DM_);
    zero_kernel<<<(B_ * H_ * S_ + 255) / 256, 256>>>(pRS, B_ * H_ * S_);

    const int M = B_ * S_;   // 8192
    mma_gemm_bias<<<dim3(DM_ / 128, M / 128), 256, SMEM_BYTES>>>(x, DM_, pWqT, DM_, bq, pQ, DM_, DM_);
    mma_gemm_bias<<<dim3(1, M / 128), 256, SMEM_BYTES>>>(x, DM_, pWkT, DM_, bk, pK, HD_, DM_);
    mma_vproj<<<dim3(1, M / 128), 256, SMEM_BYTES>>>(x, pWvT, bv, pVt);

    mma_scores<<<dim3(S_ / 128, S_ / 128, B_ * H_), 256, SMEM_BYTES>>>(pQ, pK, scores, pRS);
    mma_softmax_pv<<<dim3(S_ / 128, B_ * H_), 256, SMEM_BYTES>>>(scores, pRS, pVt, pAttn);

    mma_gemm_bias<<<dim3(DM_ / 128, M / 128), 256, SMEM_BYTES>>>(pAttn, DM_, pWoT, DM_, bo, out, DM_, DM_);
}

// round 4
// speedup vs baseline: 1.9933x; 1.1123x over previous
#include <cuda_runtime.h>
#include <cuda_bf16.h>
#include <cstdint>

// Problem dims
#define B_  4
#define S_  2048
#define DM_ 2048
#define H_  16
#define HD_ 128
#define SCALE_ 0.08838834764831843f   // 1/sqrt(128)

// ---------------- scratch (__device__ globals: allocation-free rule) ----------------
__device__ float g_Q[(size_t)B_ * S_ * DM_];        // 64 MB
__device__ float g_K[(size_t)B_ * S_ * HD_];        // 4 MB  [B*S,128] K-major
__device__ float g_Vt[(size_t)B_ * HD_ * S_];       // 4 MB  [B][128][2048]
__device__ float g_attn[(size_t)B_ * S_ * DM_];     // 64 MB
__device__ float g_rowsum[(size_t)B_ * H_ * S_];    // 0.5 MB
__device__ float g_WqT[(size_t)DM_ * DM_];
__device__ float g_WkT[(size_t)HD_ * DM_];
__device__ float g_WvT[(size_t)HD_ * DM_];
__device__ float g_WoT[(size_t)DM_ * DM_];

// ---------------- smem layout ----------------
// Double-buffered operands: stage = {Ah, Al, Bh, Bl}, each 128 x 40 bf16 = 10240 B.
// Staging fp32 128x132 (67584 B) unions with buffers after compute loop.
#define TILE_B     10240
#define STAGE_BYTES (4 * TILE_B)          // 40960
#define AUX_OFF    81920
#define RED_OFF    82432
#define SMEM_BYTES 83456
#define LDT 40            // padded smem row length (bf16 elems), conflict-free for ldsm

// ---------------- helpers ----------------
__device__ __forceinline__ uint32_t smem_u32(const void* p) {
    uint32_t a;
    asm("{ .reg .u64 t; cvta.to.shared.u64 t, %1; cvt.u32.u64 %0, t; }" : "=r"(a) : "l"(p));
    return a;
}
__device__ __forceinline__ void ldsm4(uint32_t* r, uint32_t a) {
    asm volatile("ldmatrix.sync.aligned.m8n8.x4.shared.b16 {%0,%1,%2,%3}, [%4];"
        : "=r"(r[0]), "=r"(r[1]), "=r"(r[2]), "=r"(r[3]) : "r"(a));
}
__device__ __forceinline__ void mma_bf16(float* d, const uint32_t* a, uint32_t b0, uint32_t b1) {
    asm volatile("mma.sync.aligned.m16n8k16.row.col.f32.bf16.bf16.f32 "
        "{%0,%1,%2,%3}, {%4,%5,%6,%7}, {%8,%9}, {%0,%1,%2,%3};"
        : "+f"(d[0]), "+f"(d[1]), "+f"(d[2]), "+f"(d[3])
        : "r"(a[0]), "r"(a[1]), "r"(a[2]), "r"(a[3]), "r"(b0), "r"(b1));
}
__device__ __forceinline__ uint32_t bits2(__nv_bfloat162 h) {
    return *reinterpret_cast<uint32_t*>(&h);
}
__device__ __forceinline__ void split4(float4 v, uint32_t& h0, uint32_t& h1,
                                       uint32_t& l0, uint32_t& l1) {
    __nv_bfloat162 a = __floats2bfloat162_rn(v.x, v.y);
    __nv_bfloat162 b = __floats2bfloat162_rn(v.z, v.w);
    float2 fa = __bfloat1622float2(a);
    float2 fb = __bfloat1622float2(b);
    __nv_bfloat162 c = __floats2bfloat162_rn(v.x - fa.x, v.y - fa.y);
    __nv_bfloat162 d = __floats2bfloat162_rn(v.z - fb.x, v.w - fb.y);
    h0 = bits2(a); h1 = bits2(b); l0 = bits2(c); l1 = bits2(d);
}

// core: acc = A[128,K] @ Bt[128,K]^T  (3-term bf16 split, double-buffered smem).
// PV: normalize A rows by rinv and write normalized values back to gmem while loading.
template<bool PV>
__device__ __forceinline__ void gemm_core(
    float (*acc)[8][4], float* __restrict__ A, size_t lda,
    const float* __restrict__ Bt, size_t ldb, int Kdim,
    char* smem, const float* __restrict__ rinv)
{
    const int tid = threadIdx.x;
    const int wid = tid >> 5, lane = tid & 31;
    const int wm = wid & 3, wn = wid >> 2;
    const int ar = lane & 15;
    const int acsel = (lane >> 4) << 3;

#pragma unroll 1
    for (int k0 = 0; k0 < Kdim; k0 += 32) {
        char* buf = smem + (((k0 >> 5) & 1) ? STAGE_BYTES : 0);
        __nv_bfloat16* Ah = (__nv_bfloat16*)(buf);
        __nv_bfloat16* Al = (__nv_bfloat16*)(buf + TILE_B);
        __nv_bfloat16* Bh = (__nv_bfloat16*)(buf + 2 * TILE_B);
        __nv_bfloat16* Bl = (__nv_bfloat16*)(buf + 3 * TILE_B);

#pragma unroll
        for (int i = 0; i < 4; i++) {
            int idx = i * 256 + tid;
            int r = idx >> 3, c = (idx & 7) << 2;
            float4 v = *(const float4*)(A + (size_t)r * lda + k0 + c);
            if (PV) {
                float ri = rinv[r];
                v.x *= ri; v.y *= ri; v.z *= ri; v.w *= ri;
                *(float4*)(A + (size_t)r * lda + k0 + c) = v;
            }
            uint32_t h0, h1, l0, l1; split4(v, h0, h1, l0, l1);
            int o = r * LDT + c;
            *(uint2*)(Ah + o) = make_uint2(h0, h1);
            *(uint2*)(Al + o) = make_uint2(l0, l1);
        }
#pragma unroll
        for (int i = 0; i < 4; i++) {
            int idx = i * 256 + tid;
            int r = idx >> 3, c = (idx & 7) << 2;
            float4 v = *(const float4*)(Bt + (size_t)r * ldb + k0 + c);
            uint32_t h0, h1, l0, l1; split4(v, h0, h1, l0, l1);
            int o = r * LDT + c;
            *(uint2*)(Bh + o) = make_uint2(h0, h1);
            *(uint2*)(Bl + o) = make_uint2(l0, l1);
        }
        __syncthreads();

#pragma unroll
        for (int kk = 0; kk < 32; kk += 16) {
            const int ac = kk + acsel;
            uint32_t aH[2][4], aL[2][4];
#pragma unroll
            for (int mt = 0; mt < 2; mt++) {
                ldsm4(aH[mt], smem_u32(Ah + (wm * 32 + mt * 16 + ar) * LDT + ac));
                ldsm4(aL[mt], smem_u32(Al + (wm * 32 + mt * 16 + ar) * LDT + ac));
            }
#pragma unroll
            for (int p = 0; p < 4; p++) {
                uint32_t bh[4], bl[4];
                ldsm4(bh, smem_u32(Bh + (wn * 64 + p * 16 + ar) * LDT + ac));
                ldsm4(bl, smem_u32(Bl + (wn * 64 + p * 16 + ar) * LDT + ac));
#pragma unroll
                for (int mt = 0; mt < 2; mt++) {
                    mma_bf16(acc[mt][2 * p],     aH[mt], bh[0], bh[2]);
                    mma_bf16(acc[mt][2 * p + 1], aH[mt], bh[1], bh[3]);
                    mma_bf16(acc[mt][2 * p],     aH[mt], bl[0], bl[2]);
                    mma_bf16(acc[mt][2 * p + 1], aH[mt], bl[1], bl[3]);
                    mma_bf16(acc[mt][2 * p],     aL[mt], bh[0], bh[2]);
                    mma_bf16(acc[mt][2 * p + 1], aL[mt], bh[1], bh[3]);
                }
            }
        }
    }
    __syncthreads();   // before staging reuses operand smem
}

// stage acc (fp32) into smem [128][132]
__device__ __forceinline__ void stage_acc(float (*acc)[8][4], float* stg, int wid, int lane) {
    int wm = wid & 3, wn = wid >> 2;
    int r0 = wm * 32 + (lane >> 2), c0 = wn * 64 + (lane & 3) * 2;
#pragma unroll
    for (int mt = 0; mt < 2; mt++)
#pragma unroll
        for (int nt = 0; nt < 8; nt++) {
            int r = r0 + mt * 16, c = c0 + nt * 8;
            *(float2*)&stg[r * 132 + c] = make_float2(acc[mt][nt][0], acc[mt][nt][1]);
            *(float2*)&stg[(r + 8) * 132 + c] = make_float2(acc[mt][nt][2], acc[mt][nt][3]);
        }
}

// ---------------- misc kernels ----------------
__global__ void transpose_kernel(const float* __restrict__ src, float* __restrict__ dst,
                                 int M, int N) {
    __shared__ float t[32][33];
    int bx = blockIdx.x * 32, by = blockIdx.y * 32;
    int x = threadIdx.x, y0 = threadIdx.y;
#pragma unroll
    for (int j = 0; j < 32; j += 8)
        t[y0 + j][x] = src[(size_t)(by + y0 + j) * N + bx + x];
    __syncthreads();
#pragma unroll
    for (int j = 0; j < 32; j += 8)
        dst[(size_t)(bx + y0 + j) * M + by + x] = t[x][y0 + j];
}
__global__ void zero_kernel(float* p, int n) {
    int i = blockIdx.x * blockDim.x + threadIdx.x;
    if (i < n) p[i] = 0.0f;
}

// ---------------- NT GEMM + bias: C[M,N] = A @ Bt^T + bias ----------------
__global__ __launch_bounds__(256, 2) void mma_gemm_bias(
    const float* __restrict__ A, size_t lda,
    const float* __restrict__ Bt, size_t ldb,
    const float* __restrict__ bias,
    float* __restrict__ C, size_t ldc, int Kdim)
{
    extern __shared__ __align__(16) char smem[];
    const int tid = threadIdx.x, wid = tid >> 5, lane = tid & 31;
    const int row0 = blockIdx.y * 128, col0 = blockIdx.x * 128;

    float* bs = (float*)(smem + AUX_OFF);
    if (tid < 128) bs[tid] = bias[col0 + tid];

    float acc[2][8][4];
#pragma unroll
    for (int i = 0; i < 2; i++)
#pragma unroll
        for (int j = 0; j < 8; j++)
#pragma unroll
            for (int q = 0; q < 4; q++) acc[i][j][q] = 0.0f;

    gemm_core<false>(acc, (float*)(A + (size_t)row0 * lda), lda,
                     Bt + (size_t)col0 * ldb, ldb, Kdim, smem, nullptr);

    float* stg = (float*)smem;
    stage_acc(acc, stg, wid, lane);
    __syncthreads();
#pragma unroll 1
    for (int i = 0; i < 16; i++) {
        int idx = i * 256 + tid;
        int rr = idx >> 5, c4 = (idx & 31) << 2;
        float4 v = *(float4*)&stg[rr * 132 + c4];
        v.x += bs[c4]; v.y += bs[c4 + 1]; v.z += bs[c4 + 2]; v.w += bs[c4 + 3];
        *(float4*)&C[(size_t)(row0 + rr) * ldc + col0 + c4] = v;
    }
}

// ---------------- V projection with transposed epilogue ----------------
__global__ __launch_bounds__(256, 2) void mma_vproj(
    const float* __restrict__ A, const float* __restrict__ Bt,
    const float* __restrict__ bias, float* __restrict__ Vt)
{
    extern __shared__ __align__(16) char smem[];
    const int tid = threadIdx.x, wid = tid >> 5, lane = tid & 31;
    const int row0 = blockIdx.y * 128;

    float* bs = (float*)(smem + AUX_OFF);
    if (tid < 128) bs[tid] = bias[tid];

    float acc[2][8][4];
#pragma unroll
    for (int i = 0; i < 2; i++)
#pragma unroll
        for (int j = 0; j < 8; j++)
#pragma unroll
            for (int q = 0; q < 4; q++) acc[i][j][q] = 0.0f;

    gemm_core<false>(acc, (float*)(A + (size_t)row0 * DM_), DM_, Bt, DM_, DM_, smem, nullptr);

    float* stg = (float*)smem;
    stage_acc(acc, stg, wid, lane);
    __syncthreads();
    int b = row0 >> 11;            // row0 / S_
    int s0 = row0 & (S_ - 1);
    float* Vb = Vt + (size_t)b * HD_ * S_;
#pragma unroll 1
    for (int i = 0; i < 64; i++) {
        int idx = i * 256 + tid;
        int m = idx & 127, n = idx >> 7;
        Vb[(size_t)n * S_ + s0 + m] = stg[m * 132 + n] + bs[n];
    }
}

// ---------------- scores: E = exp(scale * Q Kt) + rowsums ----------------
__global__ __launch_bounds__(256, 2) void mma_scores(
    const float* __restrict__ Q, const float* __restrict__ Kb,
    float* __restrict__ scores, float* __restrict__ rowsum)
{
    extern __shared__ __align__(16) char smem[];
    const int tid = threadIdx.x, wid = tid >> 5, lane = tid & 31;
    const int bh = blockIdx.z;
    const int b = bh >> 4, h = bh & 15;
    const int row0 = blockIdx.y * 128, col0 = blockIdx.x * 128;

    float acc[2][8][4];
#pragma unroll
    for (int i = 0; i < 2; i++)
#pragma unroll
        for (int j = 0; j < 8; j++)
#pragma unroll
            for (int q = 0; q < 4; q++) acc[i][j][q] = 0.0f;

    gemm_core<false>(acc,
        (float*)(Q + ((size_t)b * S_ + row0) * DM_ + h * HD_), DM_,
        Kb + ((size_t)b * S_ + col0) * HD_, HD_, HD_, smem, nullptr);

    // exp transform + staging + register row-sums
    float* stg = (float*)smem;
    float* red = (float*)(smem + RED_OFF);
    const int wm = wid & 3, wn = wid >> 2;
    const int r0 = wm * 32 + (lane >> 2), c0 = wn * 64 + (lane & 3) * 2;
    float sums[2][2] = {{0.f, 0.f}, {0.f, 0.f}};
#pragma unroll
    for (int mt = 0; mt < 2; mt++)
#pragma unroll
        for (int nt = 0; nt < 8; nt++) {
            float e0 = __expf(acc[mt][nt][0] * SCALE_);
            float e1 = __expf(acc[mt][nt][1] * SCALE_);
            float e2 = __expf(acc[mt][nt][2] * SCALE_);
            float e3 = __expf(acc[mt][nt][3] * SCALE_);
            int r = r0 + mt * 16, c = c0 + nt * 8;
            *(float2*)&stg[r * 132 + c] = make_float2(e0, e1);
            *(float2*)&stg[(r + 8) * 132 + c] = make_float2(e2, e3);
            sums[mt][0] += e0 + e1;
            sums[mt][1] += e2 + e3;
        }
#pragma unroll
    for (int mt = 0; mt < 2; mt++)
#pragma unroll
        for (int hh = 0; hh < 2; hh++) {
            float v = sums[mt][hh];
            v += __shfl_xor_sync(0xFFFFFFFFu, v, 1);
            v += __shfl_xor_sync(0xFFFFFFFFu, v, 2);
            sums[mt][hh] = v;
        }
    if ((lane & 3) == 0) {
#pragma unroll
        for (int mt = 0; mt < 2; mt++)
#pragma unroll
            for (int hh = 0; hh < 2; hh++)
                red[(wm * 32 + mt * 16 + hh * 8 + (lane >> 2)) * 2 + wn] = sums[mt][hh];
    }
    __syncthreads();
    if (tid < 128)
        atomicAdd(&rowsum[(size_t)bh * S_ + row0 + tid], red[tid * 2] + red[tid * 2 + 1]);

    float* Crow = scores + ((size_t)bh * S_ + row0) * S_ + col0;
#pragma unroll 1
    for (int i = 0; i < 16; i++) {
        int idx = i * 256 + tid;
        int rr = idx >> 5, c4 = (idx & 31) << 2;
        *(float4*)&Crow[(size_t)rr * S_ + c4] = *(float4*)&stg[rr * 132 + c4];
    }
}

// ---------------- normalize scores in place + PV ----------------
__global__ __launch_bounds__(256, 2) void mma_softmax_pv(
    float* __restrict__ scores, const float* __restrict__ rowsum,
    const float* __restrict__ Vt, float* __restrict__ attn)
{
    extern __shared__ __align__(16) char smem[];
    const int tid = threadIdx.x, wid = tid >> 5, lane = tid & 31;
    const int bh = blockIdx.y;
    const int b = bh >> 4, h = bh & 15;
    const int row0 = blockIdx.x * 128;

    float* rinv = (float*)(smem + AUX_OFF);
    if (tid < 128) rinv[tid] = 1.0f / rowsum[(size_t)bh * S_ + row0 + tid];
    __syncthreads();

    float acc[2][8][4];
#pragma unroll
    for (int i = 0; i < 2; i++)
#pragma unroll
        for (int j = 0; j < 8; j++)
#pragma unroll
            for (int q = 0; q < 4; q++) acc[i][j][q] = 0.0f;

    gemm_core<true>(acc,
        scores + ((size_t)bh * S_ + row0) * S_, S_,
        Vt + (size_t)b * HD_ * S_, S_, S_, smem, rinv);

    float* stg = (float*)smem;
    stage_acc(acc, stg, wid, lane);
    __syncthreads();
    float* Cb = attn + ((size_t)b * S_ + row0) * DM_ + h * HD_;
#pragma unroll 1
    for (int i = 0; i < 16; i++) {
        int idx = i * 256 + tid;
        int rr = idx >> 5, c4 = (idx & 31) << 2;
        *(float4*)&Cb[(size_t)rr * DM_ + c4] = *(float4*)&stg[rr * 132 + c4];
    }
}

// ---------------- launch ----------------
extern "C" void kernel_launch(void* const* d_in, const int* in_sizes, int n_in,
                              void* d_out, int out_size)
{
    const float* x  = (const float*)d_in[0];
    const float* Wq = (const float*)d_in[1];
    const float* bq = (const float*)d_in[2];
    const float* Wk = (const float*)d_in[3];
    const float* bk = (const float*)d_in[4];
    const float* Wv = (const float*)d_in[5];
    const float* bv = (const float*)d_in[6];
    const float* Wo = (const float*)d_in[7];
    const float* bo = (const float*)d_in[8];

    float* out = (float*)d_out;
    float* scores = out + (size_t)B_ * S_ * DM_;

    float *pQ, *pK, *pVt, *pAttn, *pRS, *pWqT, *pWkT, *pWvT, *pWoT;
    cudaGetSymbolAddress((void**)&pQ, g_Q);
    cudaGetSymbolAddress((void**)&pK, g_K);
    cudaGetSymbolAddress((void**)&pVt, g_Vt);
    cudaGetSymbolAddress((void**)&pAttn, g_attn);
    cudaGetSymbolAddress((void**)&pRS, g_rowsum);
    cudaGetSymbolAddress((void**)&pWqT, g_WqT);
    cudaGetSymbolAddress((void**)&pWkT, g_WkT);
    cudaGetSymbolAddress((void**)&pWvT, g_WvT);
    cudaGetSymbolAddress((void**)&pWoT, g_WoT);

    static int smem_set = 0;
    if (!smem_set) {
        cudaFuncSetAttribute(mma_gemm_bias, cudaFuncAttributeMaxDynamicSharedMemorySize, SMEM_BYTES);
        cudaFuncSetAttribute(mma_vproj, cudaFuncAttributeMaxDynamicSharedMemorySize, SMEM_BYTES);
        cudaFuncSetAttribute(mma_scores, cudaFuncAttributeMaxDynamicSharedMemorySize, SMEM_BYTES);
        cudaFuncSetAttribute(mma_softmax_pv, cudaFuncAttributeMaxDynamicSharedMemorySize, SMEM_BYTES);
        smem_set = 1;
    }

    transpose_kernel<<<dim3(DM_ / 32, DM_ / 32), dim3(32, 8)>>>(Wq, pWqT, DM_, DM_);
    transpose_kernel<<<dim3(HD_ / 32, DM_ / 32), dim3(32, 8)>>>(Wk, pWkT, DM_, HD_);
    transpose_kernel<<<dim3(HD_ / 32, DM_ / 32), dim3(32, 8)>>>(Wv, pWvT, DM_, HD_);
    transpose_kernel<<<dim3(DM_ / 32, DM_ / 32), dim3(32, 8)>>>(Wo, pWoT, DM_, DM_);
    zero_kernel<<<(B_ * H_ * S_ + 255) / 256, 256>>>(pRS, B_ * H_ * S_);

    const int M = B_ * S_;   // 8192
    mma_gemm_bias<<<dim3(DM_ / 128, M / 128), 256, SMEM_BYTES>>>(x, DM_, pWqT, DM_, bq, pQ, DM_, DM_);
    mma_gemm_bias<<<dim3(1, M / 128), 256, SMEM_BYTES>>>(x, DM_, pWkT, DM_, bk, pK, HD_, DM_);
    mma_vproj<<<dim3(1, M / 128), 256, SMEM_BYTES>>>(x, pWvT, bv, pVt);

    mma_scores<<<dim3(S_ / 128, S_ / 128, B_ * H_), 256, SMEM_BYTES>>>(pQ, pK, scores, pRS);
    mma_softmax_pv<<<dim3(S_ / 128, B_ * H_), 256, SMEM_BYTES>>>(scores, pRS, pVt, pAttn);

    mma_gemm_bias<<<dim3(DM_ / 128, M / 128), 256, SMEM_BYTES>>>(pAttn, DM_, pWoT, DM_, bo, out, DM_, DM_);
}